// round 5
// baseline (speedup 1.0000x reference)
#include <cuda_runtime.h>
#include <math_constants.h>

// Chamfer loss: N=8, V=4096, C=3.
// min_j ||q - t_j||^2 = 2*w_q - 2*max_j (q . t_j - w_tj),  w_p = 0.5*||p||^2.
// Packed fp32x2 FFMA inner loop, PTS=4 queries/thread, register
// double-buffered smem reads (hide LDS latency in-warp), TSPLIT=16
// target chunks -> 2048 blocks for smooth waves. Cross-block combine +
// final reduction fused via counters (deterministic order).

#define NB 8
#define VPTS 4096
#define THREADS 128
#define PTS 4
#define QCHUNK (THREADS * PTS)          // 512 queries per block
#define NQ (VPTS / QCHUNK)              // 8
#define TSPLIT 16
#define TCHUNK (VPTS / TSPLIT)          // 256 targets per block
#define NCHUNKS (2 * NB * NQ)           // 128 query chunks
#define NQTOT (2 * NB * VPTS)           // 65536 queries
#define SPAD 4                          // prefetch overread pad

__device__ float    g_pmax[NQTOT * TSPLIT];   // [qflat][tchunk] (4 MB)
__device__ unsigned g_cnt[NCHUNKS];           // zero-init; reset after use
__device__ float    g_qpart[NCHUNKS];
__device__ unsigned g_cnt_final;              // zero-init; reset after use

typedef unsigned long long u64;

__device__ __forceinline__ u64 dup2(float v) {
    u64 r;
    asm("mov.b64 %0, {%1, %1};" : "=l"(r) : "f"(v));
    return r;
}
__device__ __forceinline__ u64 ffma2(u64 a, u64 b, u64 c) {
    u64 d;
    asm("fma.rn.f32x2 %0, %1, %2, %3;" : "=l"(d) : "l"(a), "l"(b), "l"(c));
    return d;
}
__device__ __forceinline__ void maxacc(float& ml, float& mh, u64 s) {
    float lo, hi;
    asm("mov.b64 {%0, %1}, %2;" : "=f"(lo), "=f"(hi) : "l"(s));
    ml = fmaxf(ml, lo);
    mh = fmaxf(mh, hi);
}

__global__ __launch_bounds__(THREADS)
void chamfer_fused(const float* __restrict__ x, const float* __restrict__ y,
                   float* __restrict__ out) {
    // SoA target tile (+pad for prefetch overread). 16B-aligned rows.
    __shared__ __align__(16) float sTx[TCHUNK + SPAD];
    __shared__ __align__(16) float sTy[TCHUNK + SPAD];
    __shared__ __align__(16) float sTz[TCHUNK + SPAD];
    __shared__ __align__(16) float sTw[TCHUNK + SPAD];

    const int qc  = blockIdx.x / TSPLIT;    // query chunk within batch
    const int tc  = blockIdx.x % TSPLIT;    // target chunk
    const int n   = blockIdx.y;
    const int dir = blockIdx.z;             // 0: query=x,target=y ; 1: swapped
    const float* __restrict__ Q = dir ? y : x;
    const float* __restrict__ T = dir ? x : y;
    const int tid = threadIdx.x;

    // Stage + pack this block's target chunk (w negated).
    const float* Tb = T + ((size_t)n * VPTS + tc * TCHUNK) * 3;
    #pragma unroll
    for (int p = tid; p < TCHUNK; p += THREADS) {
        float a = Tb[3 * p], b = Tb[3 * p + 1], c = Tb[3 * p + 2];
        sTx[p] = a; sTy[p] = b; sTz[p] = c;
        sTw[p] = -0.5f * (a * a + b * b + c * c);
    }
    if (tid < SPAD) {  // deterministic pad (never used in results)
        sTx[TCHUNK + tid] = 0.f; sTy[TCHUNK + tid] = 0.f;
        sTz[TCHUNK + tid] = 0.f; sTw[TCHUNK + tid] = 0.f;
    }
    __syncthreads();

    // Each thread owns PTS=4 query points (tid + p*THREADS).
    const int qbase = n * VPTS + qc * QCHUNK + tid;
    u64 qx2[PTS], qy2[PTS], qz2[PTS];
    float qw[PTS];
    #pragma unroll
    for (int p = 0; p < PTS; p++) {
        const float* qp = Q + (size_t)(qbase + p * THREADS) * 3;
        float a = qp[0], b = qp[1], c = qp[2];
        qx2[p] = dup2(a); qy2[p] = dup2(b); qz2[p] = dup2(c);
        qw[p] = 0.5f * (a * a + b * b + c * c);
    }

    float mAl[PTS], mAh[PTS], mBl[PTS], mBh[PTS];
    #pragma unroll
    for (int p = 0; p < PTS; p++)
        mAl[p] = mAh[p] = mBl[p] = mBh[p] = -CUDART_INF_F;

    // Register double-buffer: prefetch j+4 while computing j.
    ulonglong2 tx = *reinterpret_cast<const ulonglong2*>(sTx);
    ulonglong2 ty = *reinterpret_cast<const ulonglong2*>(sTy);
    ulonglong2 tz = *reinterpret_cast<const ulonglong2*>(sTz);
    ulonglong2 tw = *reinterpret_cast<const ulonglong2*>(sTw);

    #pragma unroll 2
    for (int j = 0; j < TCHUNK; j += 4) {
        const ulonglong2 ntx = *reinterpret_cast<const ulonglong2*>(sTx + j + 4);
        const ulonglong2 nty = *reinterpret_cast<const ulonglong2*>(sTy + j + 4);
        const ulonglong2 ntz = *reinterpret_cast<const ulonglong2*>(sTz + j + 4);
        const ulonglong2 ntw = *reinterpret_cast<const ulonglong2*>(sTw + j + 4);
        #pragma unroll
        for (int p = 0; p < PTS; p++) {
            u64 sA = ffma2(qz2[p], tz.x, tw.x);
            sA = ffma2(qy2[p], ty.x, sA);
            sA = ffma2(qx2[p], tx.x, sA);
            maxacc(mAl[p], mAh[p], sA);
            u64 sB = ffma2(qz2[p], tz.y, tw.y);
            sB = ffma2(qy2[p], ty.y, sB);
            sB = ffma2(qx2[p], tx.y, sB);
            maxacc(mBl[p], mBh[p], sB);
        }
        tx = ntx; ty = nty; tz = ntz; tw = ntw;
    }

    // Per-query partial max for this target chunk -> global.
    const int qflat0 = (dir * NB + n) * VPTS + qc * QCHUNK + tid;
    #pragma unroll
    for (int p = 0; p < PTS; p++) {
        float m = fmaxf(fmaxf(mAl[p], mAh[p]), fmaxf(mBl[p], mBh[p]));
        g_pmax[(size_t)(qflat0 + p * THREADS) * TSPLIT + tc] = m;
    }
    __threadfence();
    __syncthreads();

    // Elect the last-arriving of the TSPLIT blocks for this query chunk.
    const int chunk = (dir * NB + n) * NQ + qc;
    __shared__ bool isLastT;
    if (tid == 0)
        isLastT = (atomicAdd(&g_cnt[chunk], 1u) == TSPLIT - 1);
    __syncthreads();

    if (isLastT) {
        __threadfence();  // acquire: see the other blocks' g_pmax writes
        float sum = 0.0f;
        #pragma unroll
        for (int p = 0; p < PTS; p++) {
            const int q = qflat0 + p * THREADS;
            const float4* pm = reinterpret_cast<const float4*>(g_pmax) +
                               (size_t)q * (TSPLIT / 4);
            float m = -CUDART_INF_F;
            #pragma unroll
            for (int k = 0; k < TSPLIT / 4; k++) {
                float4 v = pm[k];
                m = fmaxf(m, fmaxf(fmaxf(v.x, v.y), fmaxf(v.z, v.w)));
            }
            sum += sqrtf(fmaxf(2.0f * (qw[p] - m), 0.0f));
        }
        // Deterministic block reduction.
        #pragma unroll
        for (int off = 16; off > 0; off >>= 1)
            sum += __shfl_down_sync(0xffffffffu, sum, off);
        __shared__ float warpsum[THREADS / 32];
        if ((tid & 31) == 0) warpsum[tid >> 5] = sum;
        __syncthreads();

        __shared__ bool isLastF;
        if (tid == 0) {
            float b = 0.0f;
            #pragma unroll
            for (int w = 0; w < THREADS / 32; w++) b += warpsum[w];
            g_qpart[chunk] = b;
            g_cnt[chunk] = 0;                 // reset for next launch
            __threadfence();
            isLastF = (atomicAdd(&g_cnt_final, 1u) == NCHUNKS - 1);
        }
        __syncthreads();

        if (isLastF) {
            __threadfence();
            // 128 chunk partials, 128 threads: 1 each, fixed order.
            float v = g_qpart[tid];
            #pragma unroll
            for (int off = 16; off > 0; off >>= 1)
                v += __shfl_down_sync(0xffffffffu, v, off);
            __shared__ float ws2[THREADS / 32];
            if ((tid & 31) == 0) ws2[tid >> 5] = v;
            __syncthreads();
            if (tid == 0) {
                float s = 0.0f;
                #pragma unroll
                for (int w = 0; w < THREADS / 32; w++) s += ws2[w];
                out[0] = s * (1.0f / (float)(NB * VPTS));
                g_cnt_final = 0;              // reset for next launch
            }
        }
    }
}

extern "C" void kernel_launch(void* const* d_in, const int* in_sizes, int n_in,
                              void* d_out, int out_size) {
    const float* x = (const float*)d_in[0];
    const float* y = (const float*)d_in[1];
    float* out = (float*)d_out;

    dim3 grid(NQ * TSPLIT, NB, 2);   // 128 x 8 x 2 = 2048 blocks
    chamfer_fused<<<grid, THREADS>>>(x, y, out);
}

// round 6
// speedup vs baseline: 1.0928x; 1.0928x over previous
#include <cuda_runtime.h>
#include <math_constants.h>

// Chamfer loss: N=8, V=4096, C=3.
// min_j ||q - t_j||^2 = 2*w_q - 2*max_j (q . t_j - w_tj),  w_p = 0.5*||p||^2.
// Packed fp32x2 FFMA inner loop, PTS=4 queries/thread, TSPLIT=8 (1024
// blocks, ~7/SM). Inner loop is COMPONENT-MAJOR / query-minor so that
// consecutive FFMA2s share the target operand -> operand-reuse cache
// drops RF bank pressure (rt 3 -> 2). Cross-block combine + final
// reduction fused via counters (deterministic order).

#define NB 8
#define VPTS 4096
#define THREADS 128
#define PTS 4
#define QCHUNK (THREADS * PTS)          // 512 queries per block
#define NQ (VPTS / QCHUNK)              // 8
#define TSPLIT 8
#define TCHUNK (VPTS / TSPLIT)          // 512 targets per block
#define NCHUNKS (2 * NB * NQ)           // 128 query chunks
#define NQTOT (2 * NB * VPTS)           // 65536 queries

__device__ float    g_pmax[NQTOT * TSPLIT];   // [qflat][tchunk]
__device__ unsigned g_cnt[NCHUNKS];           // zero-init; reset after use
__device__ float    g_qpart[NCHUNKS];
__device__ unsigned g_cnt_final;              // zero-init; reset after use

typedef unsigned long long u64;

__device__ __forceinline__ u64 dup2(float v) {
    u64 r;
    asm("mov.b64 %0, {%1, %1};" : "=l"(r) : "f"(v));
    return r;
}
__device__ __forceinline__ u64 ffma2(u64 a, u64 b, u64 c) {
    u64 d;
    asm("fma.rn.f32x2 %0, %1, %2, %3;" : "=l"(d) : "l"(a), "l"(b), "l"(c));
    return d;
}
__device__ __forceinline__ void maxacc(float& ml, float& mh, u64 s) {
    float lo, hi;
    asm("mov.b64 {%0, %1}, %2;" : "=f"(lo), "=f"(hi) : "l"(s));
    ml = fmaxf(ml, lo);
    mh = fmaxf(mh, hi);
}

// SoA target tile: sTx | sTy | sTz | sTw(= -0.5*||t||^2)
extern __shared__ float smem[];

__global__ __launch_bounds__(THREADS)
void chamfer_fused(const float* __restrict__ x, const float* __restrict__ y,
                   float* __restrict__ out) {
    const int qc  = blockIdx.x / TSPLIT;    // query chunk within batch
    const int tc  = blockIdx.x % TSPLIT;    // target chunk
    const int n   = blockIdx.y;
    const int dir = blockIdx.z;             // 0: query=x,target=y ; 1: swapped
    const float* __restrict__ Q = dir ? y : x;
    const float* __restrict__ T = dir ? x : y;
    const int tid = threadIdx.x;

    float* sTx = smem;
    float* sTy = smem + TCHUNK;
    float* sTz = smem + 2 * TCHUNK;
    float* sTw = smem + 3 * TCHUNK;

    // Stage + pack this block's target chunk (w negated).
    const float* Tb = T + ((size_t)n * VPTS + tc * TCHUNK) * 3;
    #pragma unroll
    for (int p = tid; p < TCHUNK; p += THREADS) {
        float a = Tb[3 * p], b = Tb[3 * p + 1], c = Tb[3 * p + 2];
        sTx[p] = a; sTy[p] = b; sTz[p] = c;
        sTw[p] = -0.5f * (a * a + b * b + c * c);
    }
    __syncthreads();

    // Each thread owns PTS=4 query points (tid + p*THREADS).
    const int qbase = n * VPTS + qc * QCHUNK + tid;
    u64 qx2[PTS], qy2[PTS], qz2[PTS];
    float qw[PTS];
    #pragma unroll
    for (int p = 0; p < PTS; p++) {
        const float* qp = Q + (size_t)(qbase + p * THREADS) * 3;
        float a = qp[0], b = qp[1], c = qp[2];
        qx2[p] = dup2(a); qy2[p] = dup2(b); qz2[p] = dup2(c);
        qw[p] = 0.5f * (a * a + b * b + c * c);
    }

    float mAl[PTS], mAh[PTS], mBl[PTS], mBh[PTS];
    #pragma unroll
    for (int p = 0; p < PTS; p++)
        mAl[p] = mAh[p] = mBl[p] = mBh[p] = -CUDART_INF_F;

    #pragma unroll 2
    for (int j = 0; j < TCHUNK; j += 4) {
        const ulonglong2 tx = *reinterpret_cast<const ulonglong2*>(sTx + j);
        const ulonglong2 ty = *reinterpret_cast<const ulonglong2*>(sTy + j);
        const ulonglong2 tz = *reinterpret_cast<const ulonglong2*>(sTz + j);
        const ulonglong2 tw = *reinterpret_cast<const ulonglong2*>(sTw + j);

        u64 s[PTS];
        // ---- A half (targets j, j+1): component-major, p-minor ----
        // Consecutive FFMA2s share the target operand -> reuse cache.
        #pragma unroll
        for (int p = 0; p < PTS; p++) s[p] = ffma2(qz2[p], tz.x, tw.x);
        #pragma unroll
        for (int p = 0; p < PTS; p++) s[p] = ffma2(qy2[p], ty.x, s[p]);
        #pragma unroll
        for (int p = 0; p < PTS; p++) s[p] = ffma2(qx2[p], tx.x, s[p]);
        #pragma unroll
        for (int p = 0; p < PTS; p++) maxacc(mAl[p], mAh[p], s[p]);

        // ---- B half (targets j+2, j+3) ----
        #pragma unroll
        for (int p = 0; p < PTS; p++) s[p] = ffma2(qz2[p], tz.y, tw.y);
        #pragma unroll
        for (int p = 0; p < PTS; p++) s[p] = ffma2(qy2[p], ty.y, s[p]);
        #pragma unroll
        for (int p = 0; p < PTS; p++) s[p] = ffma2(qx2[p], tx.y, s[p]);
        #pragma unroll
        for (int p = 0; p < PTS; p++) maxacc(mBl[p], mBh[p], s[p]);
    }

    // Per-query partial max for this target chunk -> global.
    const int qflat0 = (dir * NB + n) * VPTS + qc * QCHUNK + tid;
    #pragma unroll
    for (int p = 0; p < PTS; p++) {
        float m = fmaxf(fmaxf(mAl[p], mAh[p]), fmaxf(mBl[p], mBh[p]));
        g_pmax[(size_t)(qflat0 + p * THREADS) * TSPLIT + tc] = m;
    }
    __threadfence();
    __syncthreads();

    // Elect the last-arriving of the TSPLIT blocks for this query chunk.
    const int chunk = (dir * NB + n) * NQ + qc;
    __shared__ bool isLastT;
    if (tid == 0)
        isLastT = (atomicAdd(&g_cnt[chunk], 1u) == TSPLIT - 1);
    __syncthreads();

    if (isLastT) {
        __threadfence();  // acquire: see the other blocks' g_pmax writes
        float sum = 0.0f;
        #pragma unroll
        for (int p = 0; p < PTS; p++) {
            const int q = qflat0 + p * THREADS;
            const float4* pm = reinterpret_cast<const float4*>(g_pmax) +
                               (size_t)q * (TSPLIT / 4);
            float m = -CUDART_INF_F;
            #pragma unroll
            for (int k = 0; k < TSPLIT / 4; k++) {
                float4 v = pm[k];
                m = fmaxf(m, fmaxf(fmaxf(v.x, v.y), fmaxf(v.z, v.w)));
            }
            sum += sqrtf(fmaxf(2.0f * (qw[p] - m), 0.0f));
        }
        // Deterministic block reduction.
        #pragma unroll
        for (int off = 16; off > 0; off >>= 1)
            sum += __shfl_down_sync(0xffffffffu, sum, off);
        __shared__ float warpsum[THREADS / 32];
        if ((tid & 31) == 0) warpsum[tid >> 5] = sum;
        __syncthreads();

        __shared__ bool isLastF;
        if (tid == 0) {
            float b = 0.0f;
            #pragma unroll
            for (int w = 0; w < THREADS / 32; w++) b += warpsum[w];
            g_qpart[chunk] = b;
            g_cnt[chunk] = 0;                 // reset for next launch
            __threadfence();
            isLastF = (atomicAdd(&g_cnt_final, 1u) == NCHUNKS - 1);
        }
        __syncthreads();

        if (isLastF) {
            __threadfence();
            // 128 chunk partials, 128 threads: 1 each, fixed order.
            float v = g_qpart[tid];
            #pragma unroll
            for (int off = 16; off > 0; off >>= 1)
                v += __shfl_down_sync(0xffffffffu, v, off);
            __shared__ float ws2[THREADS / 32];
            if ((tid & 31) == 0) ws2[tid >> 5] = v;
            __syncthreads();
            if (tid == 0) {
                float s = 0.0f;
                #pragma unroll
                for (int w = 0; w < THREADS / 32; w++) s += ws2[w];
                out[0] = s * (1.0f / (float)(NB * VPTS));
                g_cnt_final = 0;              // reset for next launch
            }
        }
    }
}

extern "C" void kernel_launch(void* const* d_in, const int* in_sizes, int n_in,
                              void* d_out, int out_size) {
    const float* x = (const float*)d_in[0];
    const float* y = (const float*)d_in[1];
    float* out = (float*)d_out;

    dim3 grid(NQ * TSPLIT, NB, 2);   // 64 x 8 x 2 = 1024 blocks
    chamfer_fused<<<grid, THREADS, 4 * TCHUNK * sizeof(float)>>>(x, y, out);
}